// round 14
// baseline (speedup 1.0000x reference)
#include <cuda_runtime.h>
#include <cuda_bf16.h>
#include <math.h>

constexpr int N  = 8388608;              // 2^23 samples (fixed by reference)
constexpr int NK = 8388608;              // 2^23 achievable uniform grid points
constexpr int BSHIFT = 9;                // 512 grid points per bucket
constexpr int NB = NK >> BSHIFT;         // 16384 buckets

constexpr int P_TPB    = 256;
constexpr int P_IPT    = 8;
constexpr int P_BLOCKS = N / (P_TPB * P_IPT);          // 4096

constexpr int S_TPB = 1024;
constexpr int S_BPT = NB / S_TPB;                      // 16 buckets per thread

// ---------------- static device scratch ------------------------------------
// 16-byte stride per bucket is load-bearing (R7/R8/R13): the LTS atomic path
// is lane-bound, and 8-byte-stride buckets share L2 chunks and serialize.
// One red.v4 per element == the measured optimum for pass1.
__device__ float4 g_hist[NB];            // {sum exp(s), sum e, sum e*s, 0} (256 KB,
                                         //  zero-init; scan kernel re-zeroes each call)

__device__ __forceinline__ int bucket_of(float t) {
    int k = __float2int_rn(t * 83886.08f);              // t * 2^23 / 100
    k = max(0, min(k, NK - 1));
    return (NK - 1 - k) >> BSHIFT;                      // ascending = desc time
}

// One 16-byte vector reduction: hist[b] += {ex, ev, ev*s, 0}
__device__ __forceinline__ void red_v4(float4* addr, float ex, float ev, float es) {
    asm volatile("red.global.add.v4.f32 [%0], {%1, %2, %3, %4};"
                 :: "l"(addr), "f"(ex), "f"(ev), "f"(es), "f"(0.0f) : "memory");
}

// Pass 1: pure load -> compute -> RED (at the REDG spread-address floor).
__global__ __launch_bounds__(P_TPB) void
pass1_kernel(const float* __restrict__ truth,
             const float* __restrict__ scores,
             float4* __restrict__ hist) {
    int base = (blockIdx.x * P_TPB + threadIdx.x) * P_IPT;
    float4 s0 = *reinterpret_cast<const float4*>(scores + base);
    float4 s1 = *reinterpret_cast<const float4*>(scores + base + 4);
    float4 t0 = *reinterpret_cast<const float4*>(truth + 2 * base);       // e t e t
    float4 t1 = *reinterpret_cast<const float4*>(truth + 2 * base + 4);
    float4 t2 = *reinterpret_cast<const float4*>(truth + 2 * base + 8);
    float4 t3 = *reinterpret_cast<const float4*>(truth + 2 * base + 12);

    float ev[8] = {t0.x, t0.z, t1.x, t1.z, t2.x, t2.z, t3.x, t3.z};
    float tm[8] = {t0.y, t0.w, t1.y, t1.w, t2.y, t2.w, t3.y, t3.w};
    float sc[8] = {s0.x, s0.y, s0.z, s0.w, s1.x, s1.y, s1.z, s1.w};

    #pragma unroll
    for (int j = 0; j < 8; ++j) {
        int   b  = bucket_of(tm[j]);
        float ex = __expf(sc[j]);
        red_v4(&hist[b], ex, ev[j], ev[j] * sc[j]);     // ev is exactly 0 or 1
    }
}

__device__ __forceinline__ double warp_incl_scan(double v) {
    #pragma unroll
    for (int d = 1; d < 32; d <<= 1) {
        double u = __shfl_up_sync(0xffffffffu, v, d);
        if ((threadIdx.x & 31) >= d) v += u;
    }
    return v;
}
__device__ __forceinline__ double warp_reduce(double v) {
    #pragma unroll
    for (int d = 16; d > 0; d >>= 1)
        v += __shfl_down_sync(0xffffffffu, v, d);
    return v;
}

// Single-block scan: no cross-block coordination at all (R12/R13 showed the
// publish/spin barrier + dependent L2 round-trips cost ~6us of pure latency).
// 1024 threads x 16 buckets: fp64 prefix via shuffles, midpoint-weighted event
// logs minus sum(e*s), histogram re-zero, final mean.
__global__ __launch_bounds__(S_TPB) void
scan_single(float4* __restrict__ hist, float* __restrict__ out) {
    __shared__ double wsh[S_TPB / 32];
    int tid  = threadIdx.x;
    int lane = tid & 31;
    int wid  = tid >> 5;
    int base = tid * S_BPT;

    float S[S_BPT], C[S_BPT], ES[S_BPT];
    #pragma unroll
    for (int j = 0; j < S_BPT; ++j) {
        float4 h = hist[base + j];
        S[j] = h.x; C[j] = h.y; ES[j] = h.z;
    }

    // thread-local sum -> block-wide exclusive prefix (two-level shuffle scan)
    double tsum = 0.0;
    #pragma unroll
    for (int j = 0; j < S_BPT; ++j) tsum += (double)S[j];

    double inc = warp_incl_scan(tsum);
    if (lane == 31) wsh[wid] = inc;
    __syncthreads();
    if (tid < 32) {
        double w  = (tid < S_TPB / 32) ? wsh[tid] : 0.0;
        double wi = warp_incl_scan(w);
        if (tid < S_TPB / 32) wsh[tid] = wi - w;        // exclusive warp offset
    }
    __syncthreads();
    double excl = wsh[wid] + (inc - tsum);

    // midpoint-weighted event logs minus sum(e*s)
    double acc = 0.0;
    #pragma unroll
    for (int j = 0; j < S_BPT; ++j) {
        double s = (double)S[j];
        if (C[j] != 0.0f)
            acc += (double)C[j] * (double)logf((float)(excl + 0.5 * s));
        acc -= (double)ES[j];
        excl += s;
    }

    // zero the histogram for the next replay (reads already done)
    float4 z = make_float4(0.f, 0.f, 0.f, 0.f);
    #pragma unroll
    for (int j = 0; j < S_BPT; ++j) hist[base + j] = z;

    // block reduce -> mean
    acc = warp_reduce(acc);
    __syncthreads();
    if (lane == 0) wsh[wid] = acc;
    __syncthreads();
    if (tid < 32) {
        double w = (tid < S_TPB / 32) ? wsh[tid] : 0.0;
        w = warp_reduce(w);
        if (tid == 0) out[0] = (float)(w / (double)N);
    }
}

extern "C" void kernel_launch(void* const* d_in, const int* in_sizes, int n_in,
                              void* d_out, int out_size) {
    const float* scores;
    const float* truth;
    if (in_sizes[0] == N) {
        scores = (const float*)d_in[0];
        truth  = (const float*)d_in[1];
    } else {
        scores = (const float*)d_in[1];
        truth  = (const float*)d_in[0];
    }
    float* out = (float*)d_out;

    float4* hist;
    cudaGetSymbolAddress((void**)&hist, g_hist);

    // hist is zero on entry: zero-initialized statically, and scan_single
    // re-zeroes it at the end of every call (stream order guarantees no race).
    pass1_kernel<<<P_BLOCKS, P_TPB>>>(truth, scores, hist);
    scan_single<<<1, S_TPB>>>(hist, out);
}

// round 15
// speedup vs baseline: 1.6838x; 1.6838x over previous
#include <cuda_runtime.h>
#include <cuda_bf16.h>
#include <math.h>

constexpr int N  = 8388608;              // 2^23 samples (fixed by reference)
constexpr int NK = 8388608;              // 2^23 achievable uniform grid points
constexpr int BSHIFT = 9;                // 512 grid points per bucket
constexpr int NB = NK >> BSHIFT;         // 16384 buckets

constexpr int TPB    = 256;
constexpr int IPT    = 8;                // elements per thread per tile
constexpr int TILE   = TPB * IPT;        // 2048 elements
constexpr int NTILES = N / TILE;         // 4096
constexpr int GRID   = 256;              // all co-resident (<=2 blocks/SM); 16 tiles each
constexpr int SCAN_BLOCKS = 64;          // blocks 0..63 run the scan phase
constexpr int SCAN_BPB    = NB / SCAN_BLOCKS;   // 256 buckets per scan block = 1/thread

// ---------------- static device scratch ------------------------------------
// 16-byte stride per bucket is load-bearing (R7/R8/R13): the LTS atomic path
// is lane-bound and 8-byte-stride buckets share L2 chunks and serialize.
__device__ float4 g_hist[NB];            // {sum exp(s), sum e, sum e*s, 0} (256 KB,
                                         //  zero-init; scan phase re-zeroes each call)
__device__ double g_agg[SCAN_BLOCKS];    // per-scan-block exp-sum aggregates
__device__ double g_part[SCAN_BLOCKS];   // per-scan-block loss partials
__device__ int    g_cnt0;                // pass1-complete barrier (GRID arrivals)
__device__ int    g_cnt1;                // aggregate-publish barrier (64 arrivals)
__device__ int    g_cnt2;                // completion counter (elects last block)

__device__ __forceinline__ int bucket_of(float t) {
    int k = __float2int_rn(t * 83886.08f);              // t * 2^23 / 100
    k = max(0, min(k, NK - 1));
    return (NK - 1 - k) >> BSHIFT;                      // ascending = desc time
}

// One 16-byte vector reduction: hist[b] += {ex, ev, ev*s, 0}
__device__ __forceinline__ void red_v4(float4* addr, float ex, float ev, float es) {
    asm volatile("red.global.add.v4.f32 [%0], {%1, %2, %3, %4};"
                 :: "l"(addr), "f"(ex), "f"(ev), "f"(es), "f"(0.0f) : "memory");
}

__device__ __forceinline__ double warp_incl_scan(double v) {
    #pragma unroll
    for (int d = 1; d < 32; d <<= 1) {
        double u = __shfl_up_sync(0xffffffffu, v, d);
        if ((threadIdx.x & 31) >= d) v += u;
    }
    return v;
}
__device__ __forceinline__ double warp_reduce(double v) {
    #pragma unroll
    for (int d = 16; d > 0; d >>= 1)
        v += __shfl_down_sync(0xffffffffu, v, d);
    return v;
}
__device__ __forceinline__ double ld_volatile_f64(const double* p) {
    double v;
    asm volatile("ld.volatile.global.f64 %0, [%1];" : "=d"(v) : "l"(p));
    return v;
}

// One persistent kernel: pass1 (histogram REDs at the lane floor) -> counter
// barrier -> scan phase on blocks 0..63 against an L2-hot histogram. No second
// launch, no ramp. All cross-block sums are parallel fixed-shape trees.
__global__ __launch_bounds__(TPB) void
fused_kernel(const float* __restrict__ truth,
             const float* __restrict__ scores,
             float4* __restrict__ hist,
             float* __restrict__ out) {
    int tid  = threadIdx.x;
    int lane = tid & 31;
    int wid  = tid >> 5;
    int bid  = blockIdx.x;

    // ---------------- pass 1: 16 tiles per block, cyclic --------------------
    for (int tile = bid; tile < NTILES; tile += GRID) {
        int base = tile * TILE + tid * IPT;
        float4 s0 = *reinterpret_cast<const float4*>(scores + base);
        float4 s1 = *reinterpret_cast<const float4*>(scores + base + 4);
        float4 t0 = *reinterpret_cast<const float4*>(truth + 2 * base);   // e t e t
        float4 t1 = *reinterpret_cast<const float4*>(truth + 2 * base + 4);
        float4 t2 = *reinterpret_cast<const float4*>(truth + 2 * base + 8);
        float4 t3 = *reinterpret_cast<const float4*>(truth + 2 * base + 12);

        float ev[8] = {t0.x, t0.z, t1.x, t1.z, t2.x, t2.z, t3.x, t3.z};
        float tm[8] = {t0.y, t0.w, t1.y, t1.w, t2.y, t2.w, t3.y, t3.w};
        float sc[8] = {s0.x, s0.y, s0.z, s0.w, s1.x, s1.y, s1.z, s1.w};

        #pragma unroll
        for (int j = 0; j < 8; ++j) {
            int   b  = bucket_of(tm[j]);
            float ex = __expf(sc[j]);
            red_v4(&hist[b], ex, ev[j], ev[j] * sc[j]); // ev is exactly 0 or 1
        }
    }

    // ---------------- barrier: all REDs visible -----------------------------
    __syncthreads();
    if (tid == 0) {
        __threadfence();
        atomicAdd(&g_cnt0, 1);
    }
    if (bid >= SCAN_BLOCKS) return;                     // non-scan blocks done

    if (tid == 0) {
        while (*((volatile int*)&g_cnt0) < GRID) { }
        __threadfence();
    }
    __syncthreads();

    // ---------------- scan phase: 1 bucket per thread -----------------------
    __shared__ double wsh[TPB / 32];
    __shared__ double agg_sh, excl_sh;
    __shared__ int    last_sh;

    int gidx = bid * SCAN_BPB + tid;
    float4 h = hist[gidx];
    double s = (double)h.x;

    // block-local inclusive scan
    double inc = warp_incl_scan(s);
    if (lane == 31) wsh[wid] = inc;
    __syncthreads();
    if (tid < 32) {
        double w  = (tid < TPB / 32) ? wsh[tid] : 0.0;
        double wi = warp_incl_scan(w);
        if (tid < TPB / 32) wsh[tid] = wi - w;          // exclusive warp offset
        if (tid == TPB / 32 - 1) agg_sh = wi;           // block aggregate
    }
    __syncthreads();

    // publish aggregate; wait until all scan blocks published
    if (tid == 0) {
        *((volatile double*)&g_agg[bid]) = agg_sh;
        __threadfence();
        atomicAdd(&g_cnt1, 1);
        while (*((volatile int*)&g_cnt1) < SCAN_BLOCKS) { }
        __threadfence();
    }
    __syncthreads();

    // cross-block exclusive offset: parallel loads + fixed-shape tree
    if (tid < 32) {
        double a = (tid      < bid) ? ld_volatile_f64(&g_agg[tid])      : 0.0;
        double b = (tid + 32 < bid) ? ld_volatile_f64(&g_agg[tid + 32]) : 0.0;
        double v = warp_reduce(a + b);
        if (tid == 0) excl_sh = v;
    }
    __syncthreads();
    double excl = excl_sh + wsh[wid] + (inc - s);

    // midpoint-weighted event log minus sum(e*s)
    double acc = 0.0;
    if (h.y != 0.0f)
        acc += (double)h.y * (double)logf((float)(excl + 0.5 * s));
    acc -= (double)h.z;

    // zero the histogram for the next replay (read already done)
    hist[gidx] = make_float4(0.f, 0.f, 0.f, 0.f);

    // block reduce of the loss partial
    acc = warp_reduce(acc);
    __syncthreads();
    if (lane == 0) wsh[wid] = acc;
    __syncthreads();
    if (tid < 32) {
        double w = (tid < TPB / 32) ? wsh[tid] : 0.0;
        w = warp_reduce(w);
        if (tid == 0) {
            *((volatile double*)&g_part[bid]) = w;
            __threadfence();
            int done = atomicAdd(&g_cnt2, 1);
            last_sh = (done == SCAN_BLOCKS - 1);
        }
    }
    __syncthreads();

    // elected last block: parallel fixed-shape reduction of 64 partials -> mean
    if (last_sh && tid < 32) {
        double v = ld_volatile_f64(&g_part[tid])
                 + ld_volatile_f64(&g_part[tid + 32]);
        v = warp_reduce(v);
        if (tid == 0) {
            out[0] = (float)(v / (double)N);
            g_cnt0 = 0;                                 // reset for next replay
            g_cnt1 = 0;
            g_cnt2 = 0;
        }
    }
}

extern "C" void kernel_launch(void* const* d_in, const int* in_sizes, int n_in,
                              void* d_out, int out_size) {
    const float* scores;
    const float* truth;
    if (in_sizes[0] == N) {
        scores = (const float*)d_in[0];
        truth  = (const float*)d_in[1];
    } else {
        scores = (const float*)d_in[1];
        truth  = (const float*)d_in[0];
    }
    float* out = (float*)d_out;

    float4* hist;
    cudaGetSymbolAddress((void**)&hist, g_hist);

    // hist is zero on entry: zero-initialized statically, and the scan phase
    // re-zeroes it at the end of every call. Counters reset by the last block.
    fused_kernel<<<GRID, TPB>>>(truth, scores, hist, out);
}